// round 3
// baseline (speedup 1.0000x reference)
#include <cuda_runtime.h>
#include <cuda_bf16.h>

// SudokuDigitsDoubles — exact boolean reduction ("naked pairs" row elimination).
//
// Per (puzzle b, row r):
//   m[c]   = 9-bit candidate mask of cell c               (mask[b,d,r,c] != 0)
//   pv[c]  = m[c] if popcount(m[c]) == 2 else 0
//   active pattern p: appears exactly twice among pv[0..8]
//   erase[c] = OR of active patterns p with p != pv[c]
//   out bit (d,c) = m[c] & ~erase[c]
//
// Round 3: occupancy push. launch_bounds(256,8) -> 32 regs / 8 CTAs/SM.
// Phase 2 is cell-parallel (648 threads-worth, ~16 live regs) instead of
// row-parallel (72 threads, 27+ live regs). Full-block path has
// compile-time trip counts so ptxas can batch independent LDGs.

static constexpr int PUZ_ELEMS = 729;     // 9 digits * 81 cells
static constexpr int PPB = 8;             // puzzles per block
static constexpr int NMASK = PPB * 81;    // 648
static constexpr int THREADS = 256;
static constexpr int ITERS = (NMASK + THREADS - 1) / THREADS;  // 3

__global__ __launch_bounds__(THREADS, 8)
void sudoku_doubles_kernel(const float* __restrict__ in,
                           float* __restrict__ out,
                           int nPuz)
{
    __shared__ int masks[NMASK];
    __shared__ int keepm[NMASK];

    const int basePuz = blockIdx.x * PPB;
    const bool full = (basePuz + PPB <= nPuz);
    const int nActive = full ? NMASK : (nPuz - basePuz) * 81;

    // ---- Phase 1: build 9-bit candidate masks (coalesced LDG.32) ----
    if (full) {
        #pragma unroll
        for (int it = 0; it < ITERS; ++it) {
            const int j = threadIdx.x + it * THREADS;
            if (j < NMASK) {
                const int pl = j / 81;
                const int rc = j % 81;
                const float* p = in + (size_t)(basePuz + pl) * PUZ_ELEMS + rc;
                int mm = 0;
                #pragma unroll
                for (int d = 0; d < 9; d++)
                    mm |= (__float_as_uint(p[d * 81]) != 0u ? 1 : 0) << d;
                masks[j] = mm;
            }
        }
    } else {
        for (int j = threadIdx.x; j < nActive; j += THREADS) {
            const int pl = j / 81;
            const int rc = j % 81;
            const float* p = in + (size_t)(basePuz + pl) * PUZ_ELEMS + rc;
            int mm = 0;
            #pragma unroll
            for (int d = 0; d < 9; d++)
                mm |= (__float_as_uint(p[d * 81]) != 0u ? 1 : 0) << d;
            masks[j] = mm;
        }
    }
    __syncthreads();

    // ---- Phase 2: cell-parallel naked-pair logic (low register footprint) ----
    #pragma unroll
    for (int it = 0; it < ITERS; ++it) {
        const int t = threadIdx.x + it * THREADS;
        if (t < nActive) {
            const int rc = t % 81;
            const int c  = rc % 9;
            const int rowBase = t - c;          // pl*81 + r*9

            int pv[9];
            #pragma unroll
            for (int k = 0; k < 9; k++) {
                const int mk = masks[rowBase + k];
                pv[k] = (__popc(mk) == 2) ? mk : 0;
            }
            const int me  = masks[rowBase + c];
            const int pve = pv[c];

            int erase = 0;
            #pragma unroll
            for (int j = 0; j < 9; j++) {
                int cc = 0;
                #pragma unroll
                for (int k = 0; k < 9; k++)
                    cc += (pv[k] == pv[j]) ? 1 : 0;
                const bool act = (pv[j] != 0) & (cc == 2) & (pv[j] != pve);
                erase |= act ? pv[j] : 0;
            }
            keepm[t] = me & ~erase;
        }
    }
    __syncthreads();

    // ---- Phase 3: expand keep masks to floats (coalesced STG.32, SEL not I2F) ----
    if (full) {
        #pragma unroll
        for (int it = 0; it < ITERS; ++it) {
            const int j = threadIdx.x + it * THREADS;
            if (j < NMASK) {
                const int pl = j / 81;
                const int rc = j % 81;
                const int k = keepm[j];
                float* p = out + (size_t)(basePuz + pl) * PUZ_ELEMS + rc;
                #pragma unroll
                for (int d = 0; d < 9; d++)
                    p[d * 81] = ((k >> d) & 1) ? 1.0f : 0.0f;
            }
        }
    } else {
        for (int j = threadIdx.x; j < nActive; j += THREADS) {
            const int pl = j / 81;
            const int rc = j % 81;
            const int k = keepm[j];
            float* p = out + (size_t)(basePuz + pl) * PUZ_ELEMS + rc;
            #pragma unroll
            for (int d = 0; d < 9; d++)
                p[d * 81] = ((k >> d) & 1) ? 1.0f : 0.0f;
        }
    }
}

extern "C" void kernel_launch(void* const* d_in, const int* in_sizes, int n_in,
                              void* d_out, int out_size)
{
    const float* mask = (const float*)d_in[0];
    float* out = (float*)d_out;
    const int nPuz = in_sizes[0] / PUZ_ELEMS;   // 32768
    const int grid = (nPuz + PPB - 1) / PPB;
    sudoku_doubles_kernel<<<grid, THREADS>>>(mask, out, nPuz);
}

// round 5
// speedup vs baseline: 1.2747x; 1.2747x over previous
#include <cuda_runtime.h>
#include <cuda_bf16.h>

// SudokuDigitsDoubles — exact boolean reduction ("naked pairs" row elimination).
//
// Per (puzzle b, row r):
//   m[c]   = 9-bit candidate mask of cell c
//   pv[c]  = m[c] if popcount(m[c]) == 2 else 0
//   active pattern: appears exactly twice among pv[0..8]
//   erase[c] = OR of active patterns p with p != pv[c]
//   out bit (d,c) = m[c] & ~erase[c]
//
// Round 5: Round-4 structure with the decode bug fixed — candidate bit is
// float bit 23 (exponent LSB: 1 for 1.0f, 0 for 0.0f), not bit 30.
// Row logic runs once per row (72 leaders) emitting {actmask, totalOr};
// per-cell keep is a 3-op fast path, rare exclusion loop for active cells.

static constexpr int PUZ_ELEMS = 729;   // 9 digits * 81 cells
static constexpr int PPB = 8;           // puzzles per block
static constexpr int NMASK = PPB * 81;  // 648
static constexpr int THREADS = 256;
static constexpr int ITERS = (NMASK + THREADS - 1) / THREADS;  // 3

__global__ __launch_bounds__(THREADS, 8)
void sudoku_doubles_kernel(const float* __restrict__ in,
                           float* __restrict__ out,
                           int nPuz)
{
    __shared__ int masks[NMASK];
    __shared__ int rowinfo[PPB * 9];   // totalOr | actmask<<16

    const int basePuz = blockIdx.x * PPB;
    const int puzCount = min(PPB, nPuz - basePuz);
    const int nActive = puzCount * 81;

    // ---- Phase 1: build 9-bit candidate masks (coalesced LDG.32) ----
    // Input values are exactly 0.0f or 1.0f; bit 23 (exponent LSB) is the bit.
    #pragma unroll
    for (int it = 0; it < ITERS; ++it) {
        const int j = threadIdx.x + it * THREADS;
        if (j < nActive) {
            const int pl = j / 81;
            const int rc = j % 81;
            const float* p = in + (size_t)(basePuz + pl) * PUZ_ELEMS + rc;
            unsigned mm = 0;
            #pragma unroll
            for (int d = 0; d < 9; d++)
                mm |= ((__float_as_uint(p[d * 81]) >> 23) & 1u) << d;
            masks[j] = (int)mm;
        }
    }
    __syncthreads();

    // ---- Phase 2: per-row summaries (72 leader threads) ----
    {
        const int t = threadIdx.x;
        if (t < puzCount * 9) {
            const int rowBase = 9 * t;   // t = pl*9 + r; rowBase = pl*81 + r*9
            int pv[9];
            #pragma unroll
            for (int k = 0; k < 9; k++) {
                const int mk = masks[rowBase + k];
                pv[k] = (__popc(mk) == 2) ? mk : 0;
            }
            int act = 0, tor = 0;
            #pragma unroll
            for (int j = 0; j < 9; j++) {
                int cc = 0;
                #pragma unroll
                for (int k = 0; k < 9; k++)
                    cc += (pv[k] == pv[j]) ? 1 : 0;
                const bool a = (pv[j] != 0) & (cc == 2);
                act |= a ? (1 << j) : 0;
                tor |= a ? pv[j] : 0;
            }
            rowinfo[t] = tor | (act << 16);
        }
    }
    __syncthreads();

    // ---- Phase 3: inline keep-mask + expand to floats (coalesced STG.32) ----
    #pragma unroll
    for (int it = 0; it < ITERS; ++it) {
        const int j = threadIdx.x + it * THREADS;
        if (j < nActive) {
            const int row = j / 9;         // pl*9 + r
            const int c   = j - 9 * row;
            const int m   = masks[j];
            const int info = rowinfo[row];
            const int act  = info >> 16;

            int erase;
            if ((act >> c) & 1) {
                // rare path: this cell holds an active pair -> exclude own pattern
                erase = 0;
                #pragma unroll
                for (int jj = 0; jj < 9; jj++) {
                    if ((act >> jj) & 1) {
                        const int pj = masks[9 * row + jj];
                        if (pj != m) erase |= pj;
                    }
                }
            } else {
                erase = info & 0xFFFF;     // totalOr of active patterns
            }
            const int keep = m & ~erase;

            const int pl = j / 81;
            const int rc = j - pl * 81;
            float* p = out + (size_t)(basePuz + pl) * PUZ_ELEMS + rc;
            #pragma unroll
            for (int d = 0; d < 9; d++)
                p[d * 81] = ((keep >> d) & 1) ? 1.0f : 0.0f;
        }
    }
}

extern "C" void kernel_launch(void* const* d_in, const int* in_sizes, int n_in,
                              void* d_out, int out_size)
{
    const float* mask = (const float*)d_in[0];
    float* out = (float*)d_out;
    const int nPuz = in_sizes[0] / PUZ_ELEMS;   // 32768
    const int grid = (nPuz + PPB - 1) / PPB;
    sudoku_doubles_kernel<<<grid, THREADS>>>(mask, out, nPuz);
}